// round 17
// baseline (speedup 1.0000x reference)
#include <cuda_runtime.h>
#include <cuda_bf16.h>
#include <cstdint>

#define B_   128
#define T_   512
#define D_   256
#define H_   512
#define G_   2048
#define K0_  768
#define K1_  1024
#define NKT0 (K0_ / 16)      // 48 ktiles
#define NKT1 (K1_ / 16)      // 64 ktiles
#define NCTA 128
#define NTHR 512
#define BH   (B_ * H_)

// dynamic smem (u32 idx): part (128 blocks * 132 floats) | weights
#define OFF_W    16896
#define SMEM_BYTES (16896 * 4 + NKT1 * 128 * 16)   // 67584 + 131072 = 198656

// ---------------- persistent device scratch -----------------------------------
// Weight fragments: [ntg(256)][ktp][s=hi/lo][lane(32)][8 bf16]  (ktile pairs)
__device__ uint4 g_Wf0[(size_t)256 * NKT0 * 2 * 16];   // 6 MB
__device__ uint4 g_Wf1[(size_t)256 * NKT1 * 2 * 16];   // 8 MB
__device__ float g_b0[G_];
__device__ float g_b1[G_];
// Activations, PRE-SPLIT fragment order: per ktile block = [mg8(8)][s=hi/lo(2)][lane(32)] uint4
__device__ uint4 g_xf[(size_t)T_ * 16 * 512];          // 64 MB
__device__ uint4 g_h0f[4][32 * 512];                   // 4-deep (L0 may lead)
__device__ uint4 g_h1f[2][32 * 512];
__device__ unsigned g_count;       // init barrier (all 128)
__device__ unsigned g_release;
__device__ unsigned g_gcnt[2];     // per-group barriers (64 CTAs each)
__device__ unsigned g_grel[2];

// ---------------- helpers -------------------------------------------------------
__device__ __forceinline__ float sigm(float v) {
    return __fdividef(1.f, 1.f + __expf(-v));
}
__device__ __forceinline__ float ftanh(float x) {
    float e = __expf(-2.f * fabsf(x));
    float t = __fdividef(1.f - e, 1.f + e);
    return copysignf(t, x);
}

__device__ __forceinline__ uint32_t pack_split(float v) {
    __nv_bfloat16 h = __float2bfloat16(v);
    __nv_bfloat16 l = __float2bfloat16(v - __bfloat162float(h));
    return (uint32_t)__bfloat16_as_ushort(h) |
           ((uint32_t)__bfloat16_as_ushort(l) << 16);
}

__device__ __forceinline__ uint32_t prmt(uint32_t a, uint32_t b, uint32_t c) {
    uint32_t r;
    asm("prmt.b32 %0, %1, %2, %3;" : "=r"(r) : "r"(a), "r"(b), "r"(c));
    return r;
}

__device__ __forceinline__ void mma16816(float* d, const uint32_t* a, uint2 b) {
    asm volatile(
        "mma.sync.aligned.m16n8k16.row.col.f32.bf16.bf16.f32 "
        "{%0,%1,%2,%3}, {%4,%5,%6,%7}, {%8,%9}, {%0,%1,%2,%3};"
        : "+f"(d[0]), "+f"(d[1]), "+f"(d[2]), "+f"(d[3])
        : "r"(a[0]), "r"(a[1]), "r"(a[2]), "r"(a[3]), "r"(b.x), "r"(b.y));
}

// full-grid barrier (init only)
__device__ __forceinline__ void gridBarrier(unsigned target) {
    __syncthreads();
    if (threadIdx.x == 0) {
        __threadfence();
        unsigned t = atomicAdd(&g_count, 1u);
        if (t == (unsigned)(NCTA - 1)) {
            g_count = 0;
            __threadfence();
            atomicAdd(&g_release, 1u);
        } else {
            while ((int)(*(volatile unsigned*)&g_release - target) < 0) {}
        }
        __threadfence();
    }
    __syncthreads();
}

// 64-CTA group barrier
__device__ __forceinline__ void groupBarrier(int g, unsigned target) {
    __syncthreads();
    if (threadIdx.x == 0) {
        __threadfence();
        unsigned t = atomicAdd(&g_gcnt[g], 1u);
        if (t == 63u) {
            g_gcnt[g] = 0;
            __threadfence();
            atomicAdd(&g_grel[g], 1u);
        } else {
            while ((int)(*(volatile unsigned*)&g_grel[g] - target) < 0) {}
        }
        __threadfence();
    }
    __syncthreads();
}

// wait until *p >= target (tid0 polls; syncthreads broadcasts)
__device__ __forceinline__ void pollGE(volatile unsigned* p, unsigned target) {
    if (threadIdx.x == 0) {
        while ((int)(*p - target) < 0) {}
        __threadfence();
    }
    __syncthreads();
}

// bf16-split store of W[np][k] into ktile-pair fragment layout (hi plane s=0, lo s=1)
__device__ __forceinline__ void wf_store(__nv_bfloat16* base, int NKTP,
                                         int np, int k, float v) {
    __nv_bfloat16 h = __float2bfloat16(v);
    __nv_bfloat16 l = __float2bfloat16(v - __bfloat162float(h));
    int ntg = np >> 3;
    int ln = ((np & 7) << 2) | ((k >> 1) & 3);
    int kt = k >> 4, ktp = kt >> 1, kh = kt & 1;
    int b = (k >> 3) & 1, e = k & 1;
    size_t o = ((((size_t)ntg * NKTP + ktp) * 2) * 32 + ln) * 8 + kh * 4 + b * 2 + e;
    base[o] = h;
    base[o + 256] = l;   // lo plane: +32 uint4
}

// ---------------- prep kernels ---------------------------------------------------
__global__ void prep_x(const float* __restrict__ x) {
    __shared__ float sx[16 * 256];
    int blk = blockIdx.x;           // t*8 + mg8
    int t = blk >> 3, mg = blk & 7;
    int tid = threadIdx.x;
    for (int i = tid; i < 16 * 256; i += 256) {
        int r = i >> 8, d = i & 255;
        sx[i] = x[(size_t)(mg * 16 + r) * T_ * D_ + (size_t)t * D_ + d];
    }
    __syncthreads();
    uint4* out = g_xf + (size_t)t * 16 * 512;
    for (int i = tid; i < 512; i += 256) {
        int kt = i >> 5, lane = i & 31;
        uint32_t hi[4], lo[4];
#pragma unroll
        for (int j = 0; j < 4; ++j) {
            int r = (lane >> 2) + (j & 1) * 8;
            int d0 = kt * 16 + (j >> 1) * 8 + ((lane & 3) << 1);
            uint32_t p0 = pack_split(sx[r * 256 + d0]);
            uint32_t p1 = pack_split(sx[r * 256 + d0 + 1]);
            hi[j] = prmt(p0, p1, 0x5410);
            lo[j] = prmt(p0, p1, 0x7632);
        }
        out[(size_t)kt * 512 + mg * 64 + lane] =
            make_uint4(hi[0], hi[1], hi[2], hi[3]);
        out[(size_t)kt * 512 + mg * 64 + 32 + lane] =
            make_uint4(lo[0], lo[1], lo[2], lo[3]);
    }
}

__global__ void prep_w0(const float* __restrict__ wx0, const float* __restrict__ projw,
                        const float* __restrict__ projb, const float* __restrict__ bx0,
                        const float* __restrict__ bh0) {
    int np = blockIdx.x;
    int jcol = np >> 2, q = np & 3;
    int n = q * H_ + jcol;
    int d = threadIdx.x;
    const float* wrow = wx0 + (size_t)n * D_;
    float acc = 0.f;
    for (int j = 0; j < D_; ++j) acc += wrow[j] * projw[(size_t)j * D_ + d];
    wf_store((__nv_bfloat16*)g_Wf0, NKT0 / 2, np, d, acc);
    if (d == 0) {
        float bb = bx0[n] + bh0[n];
        for (int j = 0; j < D_; ++j) bb += wrow[j] * projb[j];
        g_b0[np] = bb;
    }
}

__global__ void prep_rest(const float* __restrict__ wh0, const float* __restrict__ wx1,
                          const float* __restrict__ wh1, const float* __restrict__ bx1,
                          const float* __restrict__ bh1) {
    const int total = G_ * H_ + G_ * K1_ + G_;
    for (int i = blockIdx.x * blockDim.x + threadIdx.x; i < total;
         i += gridDim.x * blockDim.x) {
        if (i < G_ * H_) {
            int np = i / H_, k = i % H_;
            int n = (np & 3) * H_ + (np >> 2);
            wf_store((__nv_bfloat16*)g_Wf0, NKT0 / 2, np, D_ + k,
                     wh0[(size_t)n * H_ + k]);
        } else if (i < G_ * H_ + G_ * K1_) {
            int r = i - G_ * H_;
            int np = r / K1_, k = r % K1_;
            int n = (np & 3) * H_ + (np >> 2);
            float v = (k < H_) ? wx1[(size_t)n * H_ + k]
                               : wh1[(size_t)n * H_ + (k - H_)];
            wf_store((__nv_bfloat16*)g_Wf1, NKT1 / 2, np, k, v);
        } else {
            int np = i - G_ * H_ - G_ * K1_;
            int n = (np & 3) * H_ + (np >> 2);
            g_b1[np] = bx1[n] + bh1[n];
        }
    }
}

// ---------------- GEMM tile: M=32/warp x N=32/CTA, 4-way K-split (R15-validated) -
template <int NKT>
__device__ __forceinline__ void gemm_tile(const uint4* __restrict__ sW4,
    const uint4* __restrict__ pA, const uint4* __restrict__ pB, int split,
    int mg, int kgrp, int lane, float acc[2][4][4]) {
    constexpr int NKTP = NKT / 2;
    constexpr int NKTH = NKT / 4;
    const int ktbase = kgrp * NKTH;

#pragma unroll
    for (int mt = 0; mt < 2; ++mt)
#pragma unroll
        for (int nt = 0; nt < 4; ++nt)
#pragma unroll
            for (int e = 0; e < 4; ++e) acc[mt][nt][e] = 0.f;

    uint4 ab[2][4];
#pragma unroll
    for (int p = 0; p < 2; ++p) {
        int kt = ktbase + p;
        const uint4* base = (kt < split) ? pA + (size_t)kt * 512
                                         : pB + (size_t)(kt - split) * 512;
#pragma unroll
        for (int mt = 0; mt < 2; ++mt) {
            const uint4* s = base + (2 * mg + mt) * 64 + lane;
            ab[p][mt * 2 + 0] = s[0];
            ab[p][mt * 2 + 1] = s[32];
        }
    }
    uint4 bh[4], bl[4];

#pragma unroll 2
    for (int kk = 0; kk < NKTH; ++kk) {
        int ktg = ktbase + kk;
        int half = kk & 1;               // ktbase even
        if (half == 0) {
            int ktp = ktg >> 1;
#pragma unroll
            for (int nt = 0; nt < 4; ++nt) {
                const uint4* wp = sW4 + (size_t)((nt * NKTP + ktp) * 2) * 32 + lane;
                bh[nt] = wp[0];
                bl[nt] = wp[32];
            }
        }
        uint4* cur = ab[kk & 1];
        // pass 1: hi·hi
#pragma unroll
        for (int mt = 0; mt < 2; ++mt)
#pragma unroll
            for (int nt = 0; nt < 4; ++nt) {
                uint2 b2 = half ? make_uint2(bh[nt].z, bh[nt].w)
                                : make_uint2(bh[nt].x, bh[nt].y);
                mma16816(acc[mt][nt], (const uint32_t*)&cur[mt * 2 + 0], b2);
            }
        // pass 2: lo·hi
#pragma unroll
        for (int mt = 0; mt < 2; ++mt)
#pragma unroll
            for (int nt = 0; nt < 4; ++nt) {
                uint2 b2 = half ? make_uint2(bh[nt].z, bh[nt].w)
                                : make_uint2(bh[nt].x, bh[nt].y);
                mma16816(acc[mt][nt], (const uint32_t*)&cur[mt * 2 + 1], b2);
            }
        // pass 3: hi·lo
#pragma unroll
        for (int mt = 0; mt < 2; ++mt)
#pragma unroll
            for (int nt = 0; nt < 4; ++nt) {
                uint2 b2 = half ? make_uint2(bl[nt].z, bl[nt].w)
                                : make_uint2(bl[nt].x, bl[nt].y);
                mma16816(acc[mt][nt], (const uint32_t*)&cur[mt * 2 + 0], b2);
            }
        if (kk + 2 < NKTH) {
            int kn = ktg + 2;
            const uint4* base = (kn < split) ? pA + (size_t)kn * 512
                                             : pB + (size_t)(kn - split) * 512;
#pragma unroll
            for (int mt = 0; mt < 2; ++mt) {
                const uint4* s = base + (2 * mg + mt) * 64 + lane;
                cur[mt * 2 + 0] = s[0];
                cur[mt * 2 + 1] = s[32];
            }
        }
    }
}

__device__ __forceinline__ void deposit(float* __restrict__ part,
                                        int mg, int kgrp, int lane,
                                        float acc[2][4][4]) {
#pragma unroll
    for (int mt = 0; mt < 2; ++mt)
#pragma unroll
        for (int nt = 0; nt < 4; ++nt) {
            int blk = ((kgrp * 4 + mg) * 2 + mt) * 4 + nt;
            *(float4*)(part + blk * 132 + lane * 4) =
                make_float4(acc[mt][nt][0], acc[mt][nt][1],
                            acc[mt][nt][2], acc[mt][nt][3]);
        }
}

// distributed epilogue + DIRECT fragment store (no bounce): thread owns
// cells (row, 2*q2) and (row, 2*q2+1) -> one hi u32 + one lo u32.
__device__ __forceinline__ void epilogue_store(const float* __restrict__ part,
    const float* __restrict__ sbias, float* cst, uint32_t* __restrict__ O,
    int lc) {
    const int tid = threadIdx.x;
    const int row = tid >> 2, q2 = tid & 3;
    const int jc0 = q2 * 2;
    const int mg2 = row >> 5, rw = row & 31;
    const int mt = (rw >> 4) & 1, rp = (rw >> 3) & 1, rlo = rw & 7;
    const int nt = q2;
    float g8[8];
#pragma unroll
    for (int e = 0; e < 8; ++e) g8[e] = 0.f;
#pragma unroll
    for (int kg = 0; kg < 4; ++kg) {
        int blk = ((kg * 4 + mg2) * 2 + mt) * 4 + nt;
        const float* bp = part + blk * 132 + rlo * 16 + rp * 2;
#pragma unroll
        for (int q = 0; q < 4; ++q) {
            float2 v = *(const float2*)(bp + q * 4);
            g8[q * 2]     += v.x;
            g8[q * 2 + 1] += v.y;
        }
    }
    uint32_t hv[2];
#pragma unroll
    for (int c2 = 0; c2 < 2; ++c2) {
        int jc = jc0 + c2;
        float iv = g8[c2 * 4 + 0] + sbias[jc * 4 + 0];
        float fv = g8[c2 * 4 + 1] + sbias[jc * 4 + 1];
        float gv = g8[c2 * 4 + 2] + sbias[jc * 4 + 2];
        float ov = g8[c2 * 4 + 3] + sbias[jc * 4 + 3];
        float cn = sigm(fv) * cst[c2] + sigm(iv) * ftanh(gv);
        cst[c2] = cn;
        hv[c2] = pack_split(sigm(ov) * ftanh(cn));
    }
    uint32_t hi = prmt(hv[0], hv[1], 0x5410);
    uint32_t lo = prmt(hv[0], hv[1], 0x7632);
    const int kt = lc >> 1, half = lc & 1;
    const int w8 = row >> 4, r16 = row & 15;
    const int rsel = r16 >> 3, rl = r16 & 7;
    const int ln = rl * 4 + q2;
    size_t idx = ((size_t)kt * 512 + w8 * 64 + ln) * 4 + half * 2 + rsel;
    O[idx] = hi;
    O[idx + 128] = lo;   // lo plane: +32 uint4 = +128 u32
}

// ---------------- persistent main kernel -----------------------------------------
// CTAs [0,64): layer0 (group 0); CTAs [64,128): layer1 (group 1).
// Per-group 64-CTA barriers; L0 may lead up to 3 phases (h0 4-buffered).
__global__ void __launch_bounds__(NTHR, 1) lstm_main() {
    extern __shared__ uint32_t smw[];
    __shared__ float s_bias[32];
    float* part = (float*)smw;
    const uint4* sW4 = (const uint4*)(smw + OFF_W);

    const int cta = blockIdx.x, tid = threadIdx.x;
    const bool isL1 = (cta >= 64);
    const int lc = isL1 ? cta - 64 : cta;
    const int lane = tid & 31, w = tid >> 5;
    const int mg = w & 3, kgrp = w >> 2;

    // snapshots BEFORE any arrivals (graph-replay safe)
    unsigned relB   = *(volatile unsigned*)&g_release;
    unsigned relB0  = *(volatile unsigned*)&g_grel[0];
    unsigned relB1  = *(volatile unsigned*)&g_grel[1];

    // load resident weight fragment slice
    {
        const uint4* src = isL1 ? g_Wf1 : g_Wf0;
        const int NKT = isL1 ? NKT1 : NKT0;
        const uint4* s = src + (size_t)lc * NKT * 128;
        uint4* d = (uint4*)(smw + OFF_W);
        for (int i = tid; i < NKT * 128; i += NTHR) d[i] = s[i];
        const float* gb = isL1 ? g_b1 : g_b0;
        if (tid < 32) s_bias[tid] = gb[lc * 32 + tid];
    }
    // zero h buffers each launch (deterministic)
    {
        uint32_t* hz0 = (uint32_t*)g_h0f;
        uint32_t* hz1 = (uint32_t*)g_h1f;
        for (int i = cta * NTHR + tid; i < 4 * 32 * 512 * 4; i += NCTA * NTHR)
            hz0[i] = 0u;
        for (int i = cta * NTHR + tid; i < 2 * 32 * 512 * 4; i += NCTA * NTHR)
            hz1[i] = 0u;
    }

    float cst[2] = {0.f, 0.f};
    unsigned gen = 0;

    gridBarrier(relB + 1);   // init barrier (all 128 CTAs)

    float acc[2][4][4];
    for (int phase = 0; phase <= T_; ++phase) {
        if (!isL1) {
            if (phase < T_) {
                int t = phase;
                gemm_tile<NKT0>(sW4, g_xf + (size_t)t * 16 * 512,
                                (const uint4*)g_h0f[(t + 3) & 3], 16,
                                mg, kgrp, lane, acc);
                deposit(part, mg, kgrp, lane, acc);
                // throttle: don't overwrite h0 buffer still read by L1
                pollGE(&g_grel[1],
                       relB1 + (phase >= 2 ? (unsigned)(phase - 2) : 0u));
                epilogue_store(part, s_bias, cst, (uint32_t*)g_h0f[t & 3], lc);
            }
            groupBarrier(0, relB0 + ++gen);
        } else {
            if (phase >= 1) {
                int t = phase - 1;
                pollGE(&g_grel[0], relB0 + (unsigned)phase);  // h0(t) published
                gemm_tile<NKT1>(sW4, (const uint4*)g_h0f[t & 3],
                                (const uint4*)g_h1f[(t + 1) & 1], 32,
                                mg, kgrp, lane, acc);
                deposit(part, mg, kgrp, lane, acc);
                __syncthreads();
                epilogue_store(part, s_bias, cst, (uint32_t*)g_h1f[t & 1], lc);
            }
            groupBarrier(1, relB1 + ++gen);
        }
    }
}

// ---------------- FC head ----------------------------------------------------------
__global__ void fc_head(const float* __restrict__ fc1w, const float* __restrict__ fc1b,
                        const float* __restrict__ fc2w, const float* __restrict__ fc2b,
                        float* __restrict__ out) {
    __shared__ float hsh[H_];
    __shared__ float hid[32];
    int b = blockIdx.x, tid = threadIdx.x;
    const uint32_t* hf = (const uint32_t*)g_h1f[1];   // t=511 odd -> buf1
#pragma unroll
    for (int rr = 0; rr < 2; ++rr) {
        int col = tid + rr * 256;
        int kt = col >> 4, k16 = col & 15;
        int half = k16 >> 3, q = (k16 >> 1) & 3, e = k16 & 1;
        int r = b & 15, mg = b >> 4;
        int lane2 = ((r & 7) << 2) | q;
        int j = half * 2 + ((r >> 3) & 1);
        size_t u32i = ((size_t)kt * 512 + mg * 64 + lane2) * 4 + j;
        uint32_t uh = hf[u32i];
        uint32_t ul = hf[u32i + 128];
        unsigned short sh = e ? (unsigned short)(uh >> 16) : (unsigned short)(uh & 0xFFFFu);
        unsigned short sl = e ? (unsigned short)(ul >> 16) : (unsigned short)(ul & 0xFFFFu);
        hsh[col] = __bfloat162float(__ushort_as_bfloat16(sh)) +
                   __bfloat162float(__ushort_as_bfloat16(sl));
    }
    __syncthreads();
    int w = tid >> 5, lane = tid & 31;
    for (int j = w; j < 32; j += 8) {
        const float* wr = fc1w + (size_t)j * H_;
        float s = 0.f;
        for (int k = lane; k < H_; k += 32) s += hsh[k] * wr[k];
#pragma unroll
        for (int off = 16; off; off >>= 1) s += __shfl_xor_sync(0xffffffffu, s, off);
        if (lane == 0) hid[j] = fmaxf(s + fc1b[j], 0.f) * fc2w[j];
    }
    __syncthreads();
    if (tid < 32) {
        float v = hid[tid];
#pragma unroll
        for (int off = 16; off; off >>= 1) v += __shfl_xor_sync(0xffffffffu, v, off);
        if (tid == 0) out[b] = v + fc2b[0];
    }
}

// ---------------- launch -------------------------------------------------------------
extern "C" void kernel_launch(void* const* d_in, const int* in_sizes, int n_in,
                              void* d_out, int out_size) {
    const float* x     = (const float*)d_in[0];
    const float* projw = (const float*)d_in[1];
    const float* projb = (const float*)d_in[2];
    const float* wx0   = (const float*)d_in[3];
    const float* bx0   = (const float*)d_in[4];
    const float* wh0   = (const float*)d_in[5];
    const float* bh0   = (const float*)d_in[6];
    const float* wx1   = (const float*)d_in[7];
    const float* bx1   = (const float*)d_in[8];
    const float* wh1   = (const float*)d_in[9];
    const float* bh1   = (const float*)d_in[10];
    const float* fc1w  = (const float*)d_in[11];
    const float* fc1b  = (const float*)d_in[12];
    const float* fc2w  = (const float*)d_in[13];
    const float* fc2b  = (const float*)d_in[14];
    float* out = (float*)d_out;

    cudaFuncSetAttribute(lstm_main, cudaFuncAttributeMaxDynamicSharedMemorySize,
                         SMEM_BYTES);

    prep_x<<<T_ * 8, 256>>>(x);
    prep_w0<<<G_, D_>>>(wx0, projw, projb, bx0, bh0);
    prep_rest<<<2048, 256>>>(wh0, wx1, wh1, bx1, bh1);
    lstm_main<<<NCTA, NTHR, SMEM_BYTES>>>();
    fc_head<<<B_, 256>>>(fc1w, fc1b, fc2w, fc2b, out);
}